// round 1
// baseline (speedup 1.0000x reference)
#include <cuda_runtime.h>

// Entmax (alpha=1.5) per row, B=2048 rows x N=32000 cols, fp32.
// Sort-free: Newton iteration on the sparsemax threshold tau*, row held in
// registers (1024 thr x 8 float4). One DRAM read + one DRAM write total.

#define NC   32000          // columns
#define NV   (NC / 4)       // 8000 float4 per row
#define TPB  1024
#define VPT  8              // float4 slots per thread (bounds-checked)
#define NEG  (-1e30f)

__global__ __launch_bounds__(TPB, 1)
void entmax_kernel(const float* __restrict__ z, float* __restrict__ out) {
    __shared__ float s_f[32];   // per-warp partial: sum / max stage
    __shared__ float s_g[32];   // per-warp partial: v (max of z<=tau)
    __shared__ int   s_i[32];   // per-warp partial: count
    __shared__ float s_bS;      // broadcast S
    __shared__ float s_bV;      // broadcast v
    __shared__ float s_bT;      // broadcast tau_new
    __shared__ int   s_bK;      // broadcast k

    const int row  = blockIdx.x;
    const int tid  = threadIdx.x;
    const int lane = tid & 31;
    const int wid  = tid >> 5;

    const float4* zr = (const float4*)(z + (long long)row * NC);
    float4*       orow = (float4*)(out + (long long)row * NC);

    // ---- Load row into registers, tracking row max ----
    float4 r[VPT];
    float lmax = NEG;
    #pragma unroll
    for (int j = 0; j < VPT; ++j) {
        const int f = tid + j * TPB;
        if (f < NV) {
            float4 v = zr[f];
            r[j] = v;
            lmax = fmaxf(lmax, fmaxf(fmaxf(v.x, v.y), fmaxf(v.z, v.w)));
        } else {
            r[j] = make_float4(NEG, NEG, NEG, NEG);
        }
    }

    // ---- Block max reduce ----
    #pragma unroll
    for (int o = 16; o; o >>= 1)
        lmax = fmaxf(lmax, __shfl_xor_sync(0xffffffffu, lmax, o));
    if (lane == 0) s_f[wid] = lmax;
    __syncthreads();
    if (tid < 32) {
        float m = s_f[tid];
        #pragma unroll
        for (int o = 16; o; o >>= 1)
            m = fmaxf(m, __shfl_xor_sync(0xffffffffu, m, o));
        if (tid == 0) s_bT = m - 1.0f;   // Newton start: f(max-1) >= 0
    }
    __syncthreads();

    float tau = s_bT;

    // ---- Newton on f(tau) = sum(relu(z - tau)) - 1 ----
    // Each iteration: k = count(z>tau), S = sum(z>tau), v = max(z<=tau).
    // tau' = (S-1)/k. Converged when k repeats (same count + monotone tau
    // => identical support set => fixed point).
    int   k_prev = -1;
    int   kf = 1;
    float Sf = 0.0f, vf = NEG;

    for (int it = 0; it < 64; ++it) {
        int   k = 0;
        float S = 0.0f;
        float v = NEG;
        #pragma unroll
        for (int j = 0; j < VPT; ++j) {
            float c;
            c = r[j].x; if (c > tau) { k++; S += c; } else v = fmaxf(v, c);
            c = r[j].y; if (c > tau) { k++; S += c; } else v = fmaxf(v, c);
            c = r[j].z; if (c > tau) { k++; S += c; } else v = fmaxf(v, c);
            c = r[j].w; if (c > tau) { k++; S += c; } else v = fmaxf(v, c);
        }
        #pragma unroll
        for (int o = 16; o; o >>= 1) {
            k += __shfl_xor_sync(0xffffffffu, k, o);
            S += __shfl_xor_sync(0xffffffffu, S, o);
            v  = fmaxf(v, __shfl_xor_sync(0xffffffffu, v, o));
        }
        if (lane == 0) { s_i[wid] = k; s_f[wid] = S; s_g[wid] = v; }
        __syncthreads();
        if (tid < 32) {
            int kk = s_i[tid]; float SS = s_f[tid]; float vv = s_g[tid];
            #pragma unroll
            for (int o = 16; o; o >>= 1) {
                kk += __shfl_xor_sync(0xffffffffu, kk, o);
                SS += __shfl_xor_sync(0xffffffffu, SS, o);
                vv  = fmaxf(vv, __shfl_xor_sync(0xffffffffu, vv, o));
            }
            if (tid == 0) {
                s_bK = kk;
                s_bS = SS;
                s_bV = vv;
                s_bT = (SS - 1.0f) / (float)kk;
            }
        }
        __syncthreads();
        const int   k_all   = s_bK;
        const float tau_new = s_bT;
        kf = k_all; Sf = s_bS; vf = s_bV;
        if (k_all == k_prev) break;     // fixed point reached
        k_prev = k_all;
        tau = tau_new;
        __syncthreads();                // protect s_* before next iter's writes
    }

    // ---- Reference quirk: cs_k = cs[k_max] (0-based) = S + v, clamped if
    // k_max == N (then v has no element: use S alone). tau_ref=(cs_k-1)/k. ----
    const float vterm   = (vf > -1e29f) ? vf : 0.0f;
    const float tau_ref = (Sf + vterm - 1.0f) / (float)kf;

    // ---- Output: relu(z - tau_ref)^1.5, branch-skipping sqrt (rows are
    // ~99.95% zeros) ----
    #pragma unroll
    for (int j = 0; j < VPT; ++j) {
        const int f = tid + j * TPB;
        if (f < NV) {
            const float4 v = r[j];
            float a = v.x - tau_ref;
            float b = v.y - tau_ref;
            float c = v.z - tau_ref;
            float d = v.w - tau_ref;
            float4 o;
            if (fmaxf(fmaxf(a, b), fmaxf(c, d)) > 0.0f) {
                a = fmaxf(a, 0.0f); b = fmaxf(b, 0.0f);
                c = fmaxf(c, 0.0f); d = fmaxf(d, 0.0f);
                o.x = a * sqrtf(a);
                o.y = b * sqrtf(b);
                o.z = c * sqrtf(c);
                o.w = d * sqrtf(d);
            } else {
                o.x = 0.0f; o.y = 0.0f; o.z = 0.0f; o.w = 0.0f;
            }
            orow[f] = o;
        }
    }
}

extern "C" void kernel_launch(void* const* d_in, const int* in_sizes, int n_in,
                              void* d_out, int out_size) {
    const float* z = (const float*)d_in[0];
    float* out = (float*)d_out;
    const int rows = in_sizes[0] / NC;
    entmax_kernel<<<rows, TPB>>>(z, out);
}

// round 2
// speedup vs baseline: 1.2672x; 1.2672x over previous
#include <cuda_runtime.h>

// Entmax (alpha=1.5) per row, B=2048 x N=32000 fp32.
// Sort-free Newton on the sparsemax threshold. Row held in registers.
// Key optimization vs v1: after one filter sweep at tau0 = rowmax-1, the
// (tiny) candidate set is compacted into shared memory and warp 0 alone
// finishes the Newton iteration with warp shuffles -- no more full-register
// sweeps or block barriers per iteration.

#define NC   32000
#define NV   (NC / 4)
#define TPB  1024
#define VPT  8
#define NEG  (-1e30f)
#define CAP  1024           // candidate buffer (typ. ~15 used)

__global__ __launch_bounds__(TPB, 1)
void entmax_kernel(const float* __restrict__ z, float* __restrict__ out) {
    __shared__ float s_f[32];
    __shared__ float s_g[32];
    __shared__ int   s_i[32];
    __shared__ float s_cand[CAP];
    __shared__ int   s_cnt;
    __shared__ float s_bS, s_bV, s_bT;
    __shared__ int   s_bK;
    __shared__ float s_tauref;

    const int tid  = threadIdx.x;
    const int lane = tid & 31;
    const int wid  = tid >> 5;

    const long long base = (long long)blockIdx.x * NC;
    const float4* zr   = (const float4*)(z + base);
    float4*       orow = (float4*)(out + base);

    // ---- Load row into registers, tracking row max ----
    float4 r[VPT];
    float lmax = NEG;
    #pragma unroll
    for (int j = 0; j < VPT; ++j) {
        const int f = tid + j * TPB;
        if (f < NV) {
            float4 v = zr[f];
            r[j] = v;
            lmax = fmaxf(lmax, fmaxf(fmaxf(v.x, v.y), fmaxf(v.z, v.w)));
        } else {
            r[j] = make_float4(NEG, NEG, NEG, NEG);
        }
    }

    // ---- Block max reduce -> tau0 = rowmax - 1 (lower bound of tau*) ----
    #pragma unroll
    for (int o = 16; o; o >>= 1)
        lmax = fmaxf(lmax, __shfl_xor_sync(0xffffffffu, lmax, o));
    if (lane == 0) s_f[wid] = lmax;
    __syncthreads();
    if (tid < 32) {
        float m = s_f[tid];
        #pragma unroll
        for (int o = 16; o; o >>= 1)
            m = fmaxf(m, __shfl_xor_sync(0xffffffffu, m, o));
        if (tid == 0) { s_bT = m - 1.0f; s_cnt = 0; }
    }
    __syncthreads();

    float tau = s_bT;
    float tau_ref = 0.0f;
    int   kprev = -1;
    bool  fast = false, done = false;

    // ---- Filter sweep(s). Typical: exactly ONE pass, cnt<=CAP, break. ----
    // Overflow path (pathological rows): behaves like the old full-sweep
    // Newton step and re-filters at the larger tau.
    for (int it = 0; it < 40; ++it) {
        int   k = 0;
        float S = 0.0f;
        float v = NEG;
        #pragma unroll
        for (int j = 0; j < VPT; ++j) {
            float c;
            c = r[j].x; if (c > tau) { k++; S += c; int id = atomicAdd(&s_cnt, 1); if (id < CAP) s_cand[id] = c; } else v = fmaxf(v, c);
            c = r[j].y; if (c > tau) { k++; S += c; int id = atomicAdd(&s_cnt, 1); if (id < CAP) s_cand[id] = c; } else v = fmaxf(v, c);
            c = r[j].z; if (c > tau) { k++; S += c; int id = atomicAdd(&s_cnt, 1); if (id < CAP) s_cand[id] = c; } else v = fmaxf(v, c);
            c = r[j].w; if (c > tau) { k++; S += c; int id = atomicAdd(&s_cnt, 1); if (id < CAP) s_cand[id] = c; } else v = fmaxf(v, c);
        }
        #pragma unroll
        for (int o = 16; o; o >>= 1) {
            k += __shfl_xor_sync(0xffffffffu, k, o);
            S += __shfl_xor_sync(0xffffffffu, S, o);
            v  = fmaxf(v, __shfl_xor_sync(0xffffffffu, v, o));
        }
        if (lane == 0) { s_i[wid] = k; s_f[wid] = S; s_g[wid] = v; }
        __syncthreads();
        if (tid < 32) {
            int kk = s_i[tid]; float SS = s_f[tid]; float vv = s_g[tid];
            #pragma unroll
            for (int o = 16; o; o >>= 1) {
                kk += __shfl_xor_sync(0xffffffffu, kk, o);
                SS += __shfl_xor_sync(0xffffffffu, SS, o);
                vv  = fmaxf(vv, __shfl_xor_sync(0xffffffffu, vv, o));
            }
            if (tid == 0) { s_bK = kk; s_bS = SS; s_bV = vv; }
        }
        __syncthreads();
        const int   K  = s_bK;
        const float Sa = s_bS;
        const float Va = s_bV;
        const int   cnt = s_cnt;

        if (cnt <= CAP) { fast = true; break; }      // common case: 1st pass
        if (K == kprev) {                             // slow-path fixed point
            const float vt = (Va > -1e29f) ? Va : 0.0f;
            tau_ref = (Sa + vt - 1.0f) / (float)K;
            done = true; break;
        }
        kprev = K;
        tau = (Sa - 1.0f) / (float)K;
        __syncthreads();                 // all reads of s_cnt/s_b* complete
        if (tid == 0) s_cnt = 0;
        __syncthreads();
    }

    if (fast) {
        // ---- Warp 0 finishes Newton on the compacted candidate set ----
        if (wid == 0) {
            const int m = (s_cnt < CAP) ? s_cnt : CAP;
            float tl = tau;
            int   kp = -1;
            int   kF = 1; float SF = 0.0f; float vcF = NEG;
            for (int itr = 0; itr < 64; ++itr) {
                int k = 0; float S = 0.0f; float vc = NEG;
                for (int i = lane; i < m; i += 32) {
                    const float c = s_cand[i];
                    if (c > tl) { k++; S += c; } else vc = fmaxf(vc, c);
                }
                #pragma unroll
                for (int o = 16; o; o >>= 1) {
                    k += __shfl_xor_sync(0xffffffffu, k, o);
                    S += __shfl_xor_sync(0xffffffffu, S, o);
                    vc = fmaxf(vc, __shfl_xor_sync(0xffffffffu, vc, o));
                }
                kF = k; SF = S; vcF = vc;
                if (k == kp) break;          // support unchanged -> fixed point
                kp = k;
                tl = (S - 1.0f) / (float)k;
            }
            // v = max over z <= tau_final: non-candidates (<= filter tau, max
            // = s_bV) plus candidates that fell below tau_final.
            const float vfin = fmaxf(vcF, s_bV);
            const float vt = (vfin > -1e29f) ? vfin : 0.0f;
            if (lane == 0) s_tauref = (SF + vt - 1.0f) / (float)kF;
        }
        __syncthreads();
        tau_ref = s_tauref;
    } else if (!done) {
        // Pathological fallback: use last broadcast values.
        const float vt = (s_bV > -1e29f) ? s_bV : 0.0f;
        tau_ref = (s_bS + vt - 1.0f) / (float)s_bK;
    }

    // ---- Output: relu(z - tau_ref)^1.5 ; rows are ~99.95% zeros ----
    #pragma unroll
    for (int j = 0; j < VPT; ++j) {
        const int f = tid + j * TPB;
        if (f < NV) {
            const float4 v = r[j];
            float a = v.x - tau_ref;
            float b = v.y - tau_ref;
            float c = v.z - tau_ref;
            float d = v.w - tau_ref;
            float4 o;
            if (fmaxf(fmaxf(a, b), fmaxf(c, d)) > 0.0f) {
                a = fmaxf(a, 0.0f); b = fmaxf(b, 0.0f);
                c = fmaxf(c, 0.0f); d = fmaxf(d, 0.0f);
                o.x = a * sqrtf(a);
                o.y = b * sqrtf(b);
                o.z = c * sqrtf(c);
                o.w = d * sqrtf(d);
            } else {
                o.x = 0.0f; o.y = 0.0f; o.z = 0.0f; o.w = 0.0f;
            }
            __stcs(&orow[f], o);    // streaming store: no reuse
        }
    }
}

extern "C" void kernel_launch(void* const* d_in, const int* in_sizes, int n_in,
                              void* d_out, int out_size) {
    const float* z = (const float*)d_in[0];
    float* out = (float*)d_out;
    const int rows = in_sizes[0] / NC;
    entmax_kernel<<<rows, TPB>>>(z, out);
}